// round 10
// baseline (speedup 1.0000x reference)
#include <cuda_runtime.h>
#include <cstdint>

// Problem constants: B=512, T=2048, I=4, H=100, O=1
#define HDIM     100
#define TLEN     2048
#define BLOCK_T  256
#define NBLOCKS  128    // 4 batches per CTA (2 groups x 2 batches) -> 512
#define PADH     128    // h row stride in smem (floats); [100,104) zero pad
#define KH       52     // columns per K-half (100 padded to 104)

// ---- packed fp32x2 ops (Blackwell FFMA2 path, only reachable via PTX) ----
__device__ __forceinline__ unsigned long long ffma2(unsigned long long a,
                                                    unsigned long long b,
                                                    unsigned long long c) {
    unsigned long long d;
    asm("fma.rn.f32x2 %0, %1, %2, %3;" : "=l"(d) : "l"(a), "l"(b), "l"(c));
    return d;
}
__device__ __forceinline__ unsigned long long fadd2(unsigned long long a,
                                                    unsigned long long b) {
    unsigned long long d;
    asm("add.rn.f32x2 %0, %1, %2;" : "=l"(d) : "l"(a), "l"(b));
    return d;
}
__device__ __forceinline__ float hsum2(unsigned long long a) {
    unsigned int lo, hi;
    asm("mov.b64 {%0, %1}, %2;" : "=r"(lo), "=r"(hi) : "l"(a));
    return __uint_as_float(lo) + __uint_as_float(hi);
}

// tanh(x) = 1 - 2/(exp2(2*log2e*x)+1)  (validated rel_err ~1e-6 over 2048 steps)
__device__ __forceinline__ float fast_tanh(float x) {
    float e, r;
    asm("ex2.approx.f32 %0, %1;" : "=f"(e) : "f"(x * 2.8853900817779268f));
    asm("rcp.approx.f32 %0, %1;" : "=f"(r) : "f"(e + 1.0f));
    return fmaf(-2.0f, r, 1.0f);
}

__device__ __forceinline__ void group_bar(int id) {
    asm volatile("bar.sync %0, %1;" :: "r"(id), "n"(128) : "memory");
}

// ============================================================================
// Persistent recurrence kernel: 128-thread group advances TWO batches with
// shared W_hh registers (two independent chains per warp). Output projection
// is dead-end post-barrier work (4-deep ring, written t, read t+2).
// ============================================================================
__global__ void __launch_bounds__(BLOCK_T, 1)
crnn_kernel(const float* __restrict__ x,      // [512, 2048, 4]
            const float* __restrict__ W_ih,   // [100, 4]
            const float* __restrict__ W_hh,   // [100, 100]
            const float* __restrict__ W_fc,   // [1, 100]
            const float* __restrict__ b_fc,   // [1]
            float* __restrict__ out)          // [512, 2048, 1]
{
    // hbuf[buf][group][local batch][PADH]
    __shared__ __align__(16) float hbuf[2][2][2][PADH];
    // ppart[ring][group][batch][warp]
    __shared__ float ppart[4][2][2][4];

    const int tid   = threadIdx.x;
    const int g     = tid >> 7;          // group 0..1
    const int lane  = tid & 31;
    const int wig   = (tid >> 5) & 3;    // warp in group
    const int praw  = wig * 16 + (lane >> 1);   // row-pair index 0..63
    const int j     = lane & 1;                  // K-half 0/1
    const bool active = (praw < 50);
    const int pc    = active ? praw : 49;        // clamp for safe loads
    const int row0  = 2 * pc;
    const int own   = row0 + j;                  // row this thread finalizes
    const int bg0   = blockIdx.x * 4 + g * 2;    // first batch of this group
    const int bg1   = bg0 + 1;
    const int barid = 1 + g;

    // zero h buffers (h0 = 0; pad [100,128) stays 0 forever)
    for (int i = tid; i < 2 * 2 * 2 * PADH; i += BLOCK_T)
        ((float*)hbuf)[i] = 0.0f;

    // ---- W_hh: 2 rows x 52-col half -> 104 regs (shared by both batches) --
    unsigned long long w0[26], w1[26];
    {
        const ulonglong2* r0p =
            reinterpret_cast<const ulonglong2*>(W_hh + row0 * HDIM + KH * j);
        const ulonglong2* r1p =
            reinterpret_cast<const ulonglong2*>(W_hh + (row0 + 1) * HDIM + KH * j);
        #pragma unroll
        for (int k = 0; k < 13; k++) {
            ulonglong2 v = r0p[k];
            w0[2 * k] = v.x;  w0[2 * k + 1] = v.y;
        }
        #pragma unroll
        for (int k = 0; k < 12; k++) {
            ulonglong2 v = r1p[k];
            w1[2 * k] = v.x;  w1[2 * k + 1] = v.y;
        }
        // row 99's upper half, last pair: would read past W_hh; matching h
        // values are the zero pad, so zero weights are exact.
        if (pc == 49 && j == 1) {
            w1[24] = 0ull; w1[25] = 0ull;
        } else {
            ulonglong2 v = r1p[12];
            w1[24] = v.x; w1[25] = v.y;
        }
    }

    const float4 wih = *reinterpret_cast<const float4*>(W_ih + own * 4);
    const float  wfc = active ? W_fc[own] : 0.0f;
    const float  bias = b_fc[0];

    const float4* xp0 = reinterpret_cast<const float4*>(x) + (size_t)bg0 * TLEN;
    const float4* xp1 = reinterpret_cast<const float4*>(x) + (size_t)bg1 * TLEN;
    float* op0 = out + (size_t)bg0 * TLEN;
    float* op1 = out + (size_t)bg1 * TLEN;

    __syncthreads();                     // init barrier (block-wide, once)

    // phase skew between the two groups of this CTA
    if (g == 1) {
        float d = 1.0f;
        #pragma unroll 1
        for (int k = 0; k < 64; k++)
            d = fmaf(d, 1.0000001f, 1e-7f);
        asm volatile("" :: "f"(d));
    }

    const float* hb0 = &hbuf[0][g][0][0];
    float*       hw0 = &hbuf[1][g][0][0];
    const float* hb1 = &hbuf[0][g][1][0];
    float*       hw1 = &hbuf[1][g][1][0];

    float4 xc0 = xp0[0];
    float4 xc1 = xp1[0];

    #pragma unroll 1
    for (int t = 0; t < TLEN; t++) {
        // write out[t-2]: partials ordered by the two intervening barriers
        if (t >= 2) {
            const int rr = (t - 2) & 3;
            if (tid == g * 128) {
                const float* q = ppart[rr][g][0];
                op0[t - 2] = q[0] + q[1] + q[2] + q[3] + bias;
            } else if (tid == g * 128 + 32) {
                const float* q = ppart[rr][g][1];
                op1[t - 2] = q[0] + q[1] + q[2] + q[3] + bias;
            }
        }

        const int tn = (t < TLEN - 1) ? (t + 1) : t;
        float4 xn0 = xp0[tn];
        float4 xn1 = xp1[tn];

        // input projections (independent of h)
        float xpj0 = xc0.x * wih.x;
        xpj0 = fmaf(xc0.y, wih.y, xpj0);
        xpj0 = fmaf(xc0.z, wih.z, xpj0);
        xpj0 = fmaf(xc0.w, wih.w, xpj0);
        float xpj1 = xc1.x * wih.x;
        xpj1 = fmaf(xc1.y, wih.y, xpj1);
        xpj1 = fmaf(xc1.z, wih.z, xpj1);
        xpj1 = fmaf(xc1.w, wih.w, xpj1);

        // two interleaved matvecs over this thread's K-half
        unsigned long long a00 = 0ull, a01 = 0ull, a10 = 0ull, a11 = 0ull;
        unsigned long long b00 = 0ull, b01 = 0ull, b10 = 0ull, b11 = 0ull;
        const ulonglong2* hva =
            reinterpret_cast<const ulonglong2*>(hb0 + KH * j);
        const ulonglong2* hvb =
            reinterpret_cast<const ulonglong2*>(hb1 + KH * j);
        #pragma unroll
        for (int k = 0; k < 13; k++) {
            ulonglong2 ha  = hva[k];
            ulonglong2 hbv = hvb[k];
            a00 = ffma2(ha.x,  w0[2 * k],     a00);
            b00 = ffma2(hbv.x, w0[2 * k],     b00);
            a01 = ffma2(ha.y,  w0[2 * k + 1], a01);
            b01 = ffma2(hbv.y, w0[2 * k + 1], b01);
            a10 = ffma2(ha.x,  w1[2 * k],     a10);
            b10 = ffma2(hbv.x, w1[2 * k],     b10);
            a11 = ffma2(ha.y,  w1[2 * k + 1], a11);
            b11 = ffma2(hbv.y, w1[2 * k + 1], b11);
        }

        // half-dot sums; combine with partner lane (other K-half)
        float s00 = hsum2(fadd2(a00, a01));
        float s01 = hsum2(fadd2(a10, a11));
        float s10 = hsum2(fadd2(b00, b01));
        float s11 = hsum2(fadd2(b10, b11));
        float u00 = s00 + __shfl_xor_sync(0xFFFFFFFFu, s00, 1);
        float u01 = s01 + __shfl_xor_sync(0xFFFFFFFFu, s01, 1);
        float u10 = s10 + __shfl_xor_sync(0xFFFFFFFFu, s10, 1);
        float u11 = s11 + __shfl_xor_sync(0xFFFFFFFFu, s11, 1);

        const float hn0 = fast_tanh((j ? u01 : u00) + xpj0);
        const float hn1 = fast_tanh((j ? u11 : u10) + xpj1);

        if (active) {
            hw0[own] = hn0;
            hw1[own] = hn1;
        }

        group_bar(barid);                // h_{t+1} published; next step may run

        // ---- output projection (dead-end; overlaps next step's matvec) ----
        float p0 = active ? hn0 * wfc : 0.0f;
        float p1 = active ? hn1 * wfc : 0.0f;
        p0 += __shfl_xor_sync(0xFFFFFFFFu, p0, 1);
        p1 += __shfl_xor_sync(0xFFFFFFFFu, p1, 1);
        p0 += __shfl_xor_sync(0xFFFFFFFFu, p0, 2);
        p1 += __shfl_xor_sync(0xFFFFFFFFu, p1, 2);
        p0 += __shfl_xor_sync(0xFFFFFFFFu, p0, 4);
        p1 += __shfl_xor_sync(0xFFFFFFFFu, p1, 4);
        p0 += __shfl_xor_sync(0xFFFFFFFFu, p0, 8);
        p1 += __shfl_xor_sync(0xFFFFFFFFu, p1, 8);
        p0 += __shfl_xor_sync(0xFFFFFFFFu, p0, 16);
        p1 += __shfl_xor_sync(0xFFFFFFFFu, p1, 16);
        if (lane == 0) {
            ppart[t & 3][g][0][wig] = p0;
            ppart[t & 3][g][1][wig] = p1;
        }

        // swap read/write buffers
        const float* tp;
        tp = hb0; hb0 = hw0; hw0 = (float*)tp;
        tp = hb1; hb1 = hw1; hw1 = (float*)tp;
        xc0 = xn0;
        xc1 = xn1;
    }

    // flush last two outputs (order the final ppart writes first)
    group_bar(barid);
    if (lane == 0 && wig == 0) {
        #pragma unroll
        for (int dt = 2; dt >= 1; dt--) {
            const int tt = TLEN - dt;
            const float* q0 = ppart[tt & 3][g][0];
            const float* q1 = ppart[tt & 3][g][1];
            op0[tt] = q0[0] + q0[1] + q0[2] + q0[3] + bias;
            op1[tt] = q1[0] + q1[1] + q1[2] + q1[3] + bias;
        }
    }
}

extern "C" void kernel_launch(void* const* d_in, const int* in_sizes, int n_in,
                              void* d_out, int out_size) {
    const float* x    = (const float*)d_in[0];  // [512,2048,4]
    const float* W_ih = (const float*)d_in[1];  // [100,4]
    const float* W_hh = (const float*)d_in[2];  // [100,100]
    const float* W_fc = (const float*)d_in[3];  // [1,100]
    const float* b_fc = (const float*)d_in[4];  // [1]
    float* out = (float*)d_out;                 // [512,2048,1]

    crnn_kernel<<<NBLOCKS, BLOCK_T>>>(x, W_ih, W_hh, W_fc, b_fc, out);
}

// round 11
// speedup vs baseline: 1.1480x; 1.1480x over previous
#include <cuda_runtime.h>
#include <cstdint>

// Problem constants: B=512, T=2048, I=4, H=100, O=1
#define HDIM     100
#define TLEN     2048
#define BLOCK_T  320    // 2 groups x (4 main warps + 1 reducer warp)
#define NBLOCKS  128    // 4 batches per CTA -> 512
#define PADH     128    // h row stride in smem (floats)
#define KH       52     // columns per K-half (100 padded to 104)

// ---- packed fp32x2 ops (Blackwell FFMA2 path, only reachable via PTX) ----
__device__ __forceinline__ unsigned long long ffma2(unsigned long long a,
                                                    unsigned long long b,
                                                    unsigned long long c) {
    unsigned long long d;
    asm("fma.rn.f32x2 %0, %1, %2, %3;" : "=l"(d) : "l"(a), "l"(b), "l"(c));
    return d;
}
__device__ __forceinline__ unsigned long long fadd2(unsigned long long a,
                                                    unsigned long long b) {
    unsigned long long d;
    asm("add.rn.f32x2 %0, %1, %2;" : "=l"(d) : "l"(a), "l"(b));
    return d;
}
__device__ __forceinline__ float hsum2(unsigned long long a) {
    unsigned int lo, hi;
    asm("mov.b64 {%0, %1}, %2;" : "=r"(lo), "=r"(hi) : "l"(a));
    return __uint_as_float(lo) + __uint_as_float(hi);
}

// tanh(x) = 1 - 2/(exp2(2*log2e*x)+1)  (validated rel_err ~1e-6 over 2048 steps)
__device__ __forceinline__ float fast_tanh(float x) {
    float e, r;
    asm("ex2.approx.f32 %0, %1;" : "=f"(e) : "f"(x * 2.8853900817779268f));
    asm("rcp.approx.f32 %0, %1;" : "=f"(r) : "f"(e + 1.0f));
    return fmaf(-2.0f, r, 1.0f);
}

// named barrier over one group's 160 threads (4 main warps + reducer warp)
__device__ __forceinline__ void group_bar(int id) {
    asm volatile("bar.sync %0, %1;" :: "r"(id), "n"(160) : "memory");
}

__global__ void __launch_bounds__(BLOCK_T, 1)
crnn_kernel(const float* __restrict__ x,      // [512, 2048, 4]
            const float* __restrict__ W_ih,   // [100, 4]
            const float* __restrict__ W_hh,   // [100, 100]
            const float* __restrict__ W_fc,   // [1, 100]
            const float* __restrict__ b_fc,   // [1]
            float* __restrict__ out)          // [512, 2048, 1]
{
    // hbuf[buf][group][local batch][PADH]
    __shared__ __align__(16) float hbuf[2][2][2][PADH];

    const int tid   = threadIdx.x;
    const int wid   = tid >> 5;
    const int lane  = tid & 31;
    const int g     = (wid >= 5);        // group 0..1
    const int wig   = wid - g * 5;       // warp in group 0..4 (4 = reducer)
    const int bg0   = blockIdx.x * 4 + g * 2;
    const int bg1   = bg0 + 1;
    const int barid = 1 + g;

    // zero h buffers (h0 = 0; pad [100,128) stays 0 forever)
    for (int i = tid; i < 2 * 2 * 2 * PADH; i += BLOCK_T)
        ((float*)hbuf)[i] = 0.0f;

    if (wig < 4) {
        // ================= MAIN WARPS: the recurrence =====================
        const int praw  = wig * 16 + (lane >> 1);   // row-pair index
        const int j     = lane & 1;                  // K-half 0/1
        const bool active = (praw < 50);
        const int pc    = active ? praw : 49;        // clamp for safe loads
        const int row0  = 2 * pc;
        const int own   = row0 + j;                  // row this thread owns

        // W_hh: 2 rows x 52-col half -> 104 regs (shared by both batches)
        unsigned long long w0[26], w1[26];
        {
            const ulonglong2* r0p =
                reinterpret_cast<const ulonglong2*>(W_hh + row0 * HDIM + KH * j);
            const ulonglong2* r1p =
                reinterpret_cast<const ulonglong2*>(W_hh + (row0 + 1) * HDIM + KH * j);
            #pragma unroll
            for (int k = 0; k < 13; k++) {
                ulonglong2 v = r0p[k];
                w0[2 * k] = v.x;  w0[2 * k + 1] = v.y;
            }
            #pragma unroll
            for (int k = 0; k < 12; k++) {
                ulonglong2 v = r1p[k];
                w1[2 * k] = v.x;  w1[2 * k + 1] = v.y;
            }
            // row 99's upper half, last pair: matching h is the zero pad
            if (pc == 49 && j == 1) {
                w1[24] = 0ull; w1[25] = 0ull;
            } else {
                ulonglong2 v = r1p[12];
                w1[24] = v.x; w1[25] = v.y;
            }
        }

        const float4 wih = *reinterpret_cast<const float4*>(W_ih + own * 4);

        const float4* xp0 = reinterpret_cast<const float4*>(x) + (size_t)bg0 * TLEN;
        const float4* xp1 = reinterpret_cast<const float4*>(x) + (size_t)bg1 * TLEN;

        __syncthreads();                 // init barrier (block-wide, once)

        const float* hb0 = &hbuf[0][g][0][0];
        float*       hw0 = &hbuf[1][g][0][0];
        const float* hb1 = &hbuf[0][g][1][0];
        float*       hw1 = &hbuf[1][g][1][0];

        float4 xc0 = xp0[0];
        float4 xc1 = xp1[0];

        #pragma unroll 1
        for (int t = 0; t < TLEN; t++) {
            const int tn = (t < TLEN - 1) ? (t + 1) : t;
            float4 xn0 = xp0[tn];
            float4 xn1 = xp1[tn];

            // input projections (independent of h)
            float xpj0 = xc0.x * wih.x;
            xpj0 = fmaf(xc0.y, wih.y, xpj0);
            xpj0 = fmaf(xc0.z, wih.z, xpj0);
            xpj0 = fmaf(xc0.w, wih.w, xpj0);
            float xpj1 = xc1.x * wih.x;
            xpj1 = fmaf(xc1.y, wih.y, xpj1);
            xpj1 = fmaf(xc1.z, wih.z, xpj1);
            xpj1 = fmaf(xc1.w, wih.w, xpj1);

            // two interleaved matvecs over this thread's K-half
            unsigned long long a00 = 0ull, a01 = 0ull, a10 = 0ull, a11 = 0ull;
            unsigned long long b00 = 0ull, b01 = 0ull, b10 = 0ull, b11 = 0ull;
            const ulonglong2* hva =
                reinterpret_cast<const ulonglong2*>(hb0 + KH * j);
            const ulonglong2* hvb =
                reinterpret_cast<const ulonglong2*>(hb1 + KH * j);
            #pragma unroll
            for (int k = 0; k < 13; k++) {
                ulonglong2 ha  = hva[k];
                ulonglong2 hbv = hvb[k];
                a00 = ffma2(ha.x,  w0[2 * k],     a00);
                b00 = ffma2(hbv.x, w0[2 * k],     b00);
                a01 = ffma2(ha.y,  w0[2 * k + 1], a01);
                b01 = ffma2(hbv.y, w0[2 * k + 1], b01);
                a10 = ffma2(ha.x,  w1[2 * k],     a10);
                b10 = ffma2(hbv.x, w1[2 * k],     b10);
                a11 = ffma2(ha.y,  w1[2 * k + 1], a11);
                b11 = ffma2(hbv.y, w1[2 * k + 1], b11);
            }

            // half-dot sums; combine with partner lane (other K-half)
            float s00 = hsum2(fadd2(a00, a01));
            float s01 = hsum2(fadd2(a10, a11));
            float s10 = hsum2(fadd2(b00, b01));
            float s11 = hsum2(fadd2(b10, b11));
            float u00 = s00 + __shfl_xor_sync(0xFFFFFFFFu, s00, 1);
            float u01 = s01 + __shfl_xor_sync(0xFFFFFFFFu, s01, 1);
            float u10 = s10 + __shfl_xor_sync(0xFFFFFFFFu, s10, 1);
            float u11 = s11 + __shfl_xor_sync(0xFFFFFFFFu, s11, 1);

            const float hn0 = fast_tanh((j ? u01 : u00) + xpj0);
            const float hn1 = fast_tanh((j ? u11 : u10) + xpj1);

            if (active) {
                hw0[own] = hn0;
                hw1[own] = hn1;
            }

            group_bar(barid);            // h_{t+1} published for this group

            // swap read/write buffers; advance x
            const float* tp;
            tp = hb0; hb0 = hw0; hw0 = (float*)tp;
            tp = hb1; hb1 = hw1; hw1 = (float*)tp;
            xc0 = xn0;
            xc1 = xn1;
        }
    } else {
        // ================= REDUCER WARP: output projection ================
        // lanes 0..24 each own 4 consecutive h entries (25*4 = 100)
        const bool ract = (lane < 25);
        float4 wf = make_float4(0.f, 0.f, 0.f, 0.f);
        if (ract)
            wf = *reinterpret_cast<const float4*>(W_fc + lane * 4);
        const float bias = b_fc[0];

        float* op0 = out + (size_t)bg0 * TLEN;
        float* op1 = out + (size_t)bg1 * TLEN;

        __syncthreads();                 // init barrier

        int cur = 0;
        #pragma unroll 1
        for (int t = 0; t < TLEN; t++) {
            group_bar(barid);            // h for step t is now in hbuf[cur^1]
            const int nb = cur ^ 1;

            float s0 = 0.0f, s1 = 0.0f;
            if (ract) {
                float4 h0 = *reinterpret_cast<const float4*>(&hbuf[nb][g][0][lane * 4]);
                float4 h1 = *reinterpret_cast<const float4*>(&hbuf[nb][g][1][lane * 4]);
                s0 = h0.x * wf.x;
                s1 = h1.x * wf.x;
                s0 = fmaf(h0.y, wf.y, s0);
                s1 = fmaf(h1.y, wf.y, s1);
                s0 = fmaf(h0.z, wf.z, s0);
                s1 = fmaf(h1.z, wf.z, s1);
                s0 = fmaf(h0.w, wf.w, s0);
                s1 = fmaf(h1.w, wf.w, s1);
            }
            s0 += __shfl_xor_sync(0xFFFFFFFFu, s0, 1);
            s1 += __shfl_xor_sync(0xFFFFFFFFu, s1, 1);
            s0 += __shfl_xor_sync(0xFFFFFFFFu, s0, 2);
            s1 += __shfl_xor_sync(0xFFFFFFFFu, s1, 2);
            s0 += __shfl_xor_sync(0xFFFFFFFFu, s0, 4);
            s1 += __shfl_xor_sync(0xFFFFFFFFu, s1, 4);
            s0 += __shfl_xor_sync(0xFFFFFFFFu, s0, 8);
            s1 += __shfl_xor_sync(0xFFFFFFFFu, s1, 8);
            s0 += __shfl_xor_sync(0xFFFFFFFFu, s0, 16);
            s1 += __shfl_xor_sync(0xFFFFFFFFu, s1, 16);
            if (lane == 0)
                op0[t] = s0 + bias;
            else if (lane == 1)  // lane 1 has the full sum too (xor tree)
                op1[t] = s1 + bias;

            cur ^= 1;
        }
    }
}

extern "C" void kernel_launch(void* const* d_in, const int* in_sizes, int n_in,
                              void* d_out, int out_size) {
    const float* x    = (const float*)d_in[0];  // [512,2048,4]
    const float* W_ih = (const float*)d_in[1];  // [100,4]
    const float* W_hh = (const float*)d_in[2];  // [100,100]
    const float* W_fc = (const float*)d_in[3];  // [1,100]
    const float* b_fc = (const float*)d_in[4];  // [1]
    float* out = (float*)d_out;                 // [512,2048,1]

    crnn_kernel<<<NBLOCKS, BLOCK_T>>>(x, W_ih, W_hh, W_fc, b_fc, out);
}

// round 13
// speedup vs baseline: 1.1651x; 1.0148x over previous
#include <cuda_runtime.h>
#include <cuda_fp16.h>
#include <cstdint>

// Problem constants: B=512, T=2048, I=4, H=100, O=1
#define HDIM     100
#define TLEN     2048
#define BLOCK_T  256
#define NBLOCKS  128    // 4 batches per CTA (2 groups x 2 batches) -> 512
#define PADH     128    // h row stride in smem (floats); pad stays 0
#define KH       52     // columns per K-half (100 padded to 104)
#define PADHS    104    // fp16 trajectory row stride (26 lanes x 4 fp16)

// hidden-state trajectory: [b][t][104] fp16. Pad [100..104) stays zero
// (zero-initialized module storage, never written) and is dotted with zero
// weights in proj_kernel. tanh output is in (-1,1): fp16-safe, 10 mantissa
// bits (8x finer than bf16, whose 3.5e-3 rel_err failed in R11).
__device__ __half Hs[(size_t)512 * TLEN * PADHS];

// ---- packed fp32x2 ops (Blackwell FFMA2 path, only reachable via PTX) ----
__device__ __forceinline__ unsigned long long ffma2(unsigned long long a,
                                                    unsigned long long b,
                                                    unsigned long long c) {
    unsigned long long d;
    asm("fma.rn.f32x2 %0, %1, %2, %3;" : "=l"(d) : "l"(a), "l"(b), "l"(c));
    return d;
}
__device__ __forceinline__ unsigned long long fadd2(unsigned long long a,
                                                    unsigned long long b) {
    unsigned long long d;
    asm("add.rn.f32x2 %0, %1, %2;" : "=l"(d) : "l"(a), "l"(b));
    return d;
}
__device__ __forceinline__ float hsum2(unsigned long long a) {
    unsigned int lo, hi;
    asm("mov.b64 {%0, %1}, %2;" : "=r"(lo), "=r"(hi) : "l"(a));
    return __uint_as_float(lo) + __uint_as_float(hi);
}

// tanh(x) = 1 - 2/(exp2(2*log2e*x)+1)  (validated rel_err ~1e-6 over 2048 steps)
__device__ __forceinline__ float fast_tanh(float x) {
    float e, r;
    asm("ex2.approx.f32 %0, %1;" : "=f"(e) : "f"(x * 2.8853900817779268f));
    asm("rcp.approx.f32 %0, %1;" : "=f"(r) : "f"(e + 1.0f));
    return fmaf(-2.0f, r, 1.0f);
}

__device__ __forceinline__ void group_bar(int id) {
    asm volatile("bar.sync %0, %1;" :: "r"(id), "n"(128) : "memory");
}

// ============================================================================
// Kernel 1: the recurrence (R8 structure, unspilled via maxblocks=1).
// 128-thread group advances TWO batches with shared W_hh registers
// (two independent dependency chains per warp).
// ============================================================================
__global__ void __launch_bounds__(BLOCK_T, 1)
crnn_step_kernel(const float* __restrict__ x,      // [512, 2048, 4]
                 const float* __restrict__ W_ih,   // [100, 4]
                 const float* __restrict__ W_hh)   // [100, 100]
{
    // hbuf[buf][group][local batch][PADH]
    __shared__ __align__(16) float hbuf[2][2][2][PADH];

    const int tid   = threadIdx.x;
    const int g     = tid >> 7;          // group 0..1
    const int lane  = tid & 31;
    const int wig   = (tid >> 5) & 3;    // warp in group
    const int praw  = wig * 16 + (lane >> 1);   // row-pair index 0..63
    const int j     = lane & 1;                  // K-half 0/1
    const bool active = (praw < 50);
    const int pc    = active ? praw : 49;        // clamp for safe loads
    const int row0  = 2 * pc;
    const int own   = row0 + j;                  // row this thread finalizes
    const int bg0   = blockIdx.x * 4 + g * 2;    // first batch of this group
    const int bg1   = bg0 + 1;
    const int barid = 1 + g;

    // zero h buffers (h0 = 0; pad [100,128) stays 0 forever)
    for (int i = tid; i < 2 * 2 * 2 * PADH; i += BLOCK_T)
        ((float*)hbuf)[i] = 0.0f;

    // ---- W_hh: 2 rows x 52-col half -> 104 regs (shared by both batches) --
    unsigned long long w0[26], w1[26];
    {
        const ulonglong2* r0p =
            reinterpret_cast<const ulonglong2*>(W_hh + row0 * HDIM + KH * j);
        const ulonglong2* r1p =
            reinterpret_cast<const ulonglong2*>(W_hh + (row0 + 1) * HDIM + KH * j);
        #pragma unroll
        for (int k = 0; k < 13; k++) {
            ulonglong2 v = r0p[k];
            w0[2 * k] = v.x;  w0[2 * k + 1] = v.y;
        }
        #pragma unroll
        for (int k = 0; k < 12; k++) {
            ulonglong2 v = r1p[k];
            w1[2 * k] = v.x;  w1[2 * k + 1] = v.y;
        }
        // row 99's upper half, last pair: would read past W_hh; matching h
        // values are the zero pad, so zero weights are exact.
        if (pc == 49 && j == 1) {
            w1[24] = 0ull; w1[25] = 0ull;
        } else {
            ulonglong2 v = r1p[12];
            w1[24] = v.x; w1[25] = v.y;
        }
    }

    const float4 wih = *reinterpret_cast<const float4*>(W_ih + own * 4);

    const float4* xp0 = reinterpret_cast<const float4*>(x) + (size_t)bg0 * TLEN;
    const float4* xp1 = reinterpret_cast<const float4*>(x) + (size_t)bg1 * TLEN;
    __half* hs0 = Hs + (size_t)bg0 * TLEN * PADHS + own;
    __half* hs1 = Hs + (size_t)bg1 * TLEN * PADHS + own;

    __syncthreads();                     // init barrier (block-wide, once)

    // small phase offset between the two groups of this CTA (as in R8)
    if (g == 1) {
        float d = 1.0f;
        #pragma unroll 1
        for (int k = 0; k < 64; k++)
            d = fmaf(d, 1.0000001f, 1e-7f);
        asm volatile("" :: "f"(d));
    }

    const float* hb0 = &hbuf[0][g][0][0];
    float*       hw0 = &hbuf[1][g][0][0];
    const float* hb1 = &hbuf[0][g][1][0];
    float*       hw1 = &hbuf[1][g][1][0];

    float4 xc0 = xp0[0];
    float4 xc1 = xp1[0];

    #pragma unroll 1
    for (int t = 0; t < TLEN; t++) {
        const int tn = (t < TLEN - 1) ? (t + 1) : t;
        float4 xn0 = xp0[tn];
        float4 xn1 = xp1[tn];

        // input projections (independent of h)
        float xpj0 = xc0.x * wih.x;
        xpj0 = fmaf(xc0.y, wih.y, xpj0);
        xpj0 = fmaf(xc0.z, wih.z, xpj0);
        xpj0 = fmaf(xc0.w, wih.w, xpj0);
        float xpj1 = xc1.x * wih.x;
        xpj1 = fmaf(xc1.y, wih.y, xpj1);
        xpj1 = fmaf(xc1.z, wih.z, xpj1);
        xpj1 = fmaf(xc1.w, wih.w, xpj1);

        // two interleaved matvecs over this thread's K-half
        unsigned long long a00 = 0ull, a01 = 0ull, a10 = 0ull, a11 = 0ull;
        unsigned long long b00 = 0ull, b01 = 0ull, b10 = 0ull, b11 = 0ull;
        const ulonglong2* hva =
            reinterpret_cast<const ulonglong2*>(hb0 + KH * j);
        const ulonglong2* hvb =
            reinterpret_cast<const ulonglong2*>(hb1 + KH * j);
        #pragma unroll
        for (int k = 0; k < 13; k++) {
            ulonglong2 ha  = hva[k];
            ulonglong2 hbv = hvb[k];
            a00 = ffma2(ha.x,  w0[2 * k],     a00);
            b00 = ffma2(hbv.x, w0[2 * k],     b00);
            a01 = ffma2(ha.y,  w0[2 * k + 1], a01);
            b01 = ffma2(hbv.y, w0[2 * k + 1], b01);
            a10 = ffma2(ha.x,  w1[2 * k],     a10);
            b10 = ffma2(hbv.x, w1[2 * k],     b10);
            a11 = ffma2(ha.y,  w1[2 * k + 1], a11);
            b11 = ffma2(hbv.y, w1[2 * k + 1], b11);
        }

        // half-dot sums; combine with partner lane (other K-half)
        float s00 = hsum2(fadd2(a00, a01));
        float s01 = hsum2(fadd2(a10, a11));
        float s10 = hsum2(fadd2(b00, b01));
        float s11 = hsum2(fadd2(b10, b11));
        float u00 = s00 + __shfl_xor_sync(0xFFFFFFFFu, s00, 1);
        float u01 = s01 + __shfl_xor_sync(0xFFFFFFFFu, s01, 1);
        float u10 = s10 + __shfl_xor_sync(0xFFFFFFFFu, s10, 1);
        float u11 = s11 + __shfl_xor_sync(0xFFFFFFFFu, s11, 1);

        const float hn0 = fast_tanh((j ? u01 : u00) + xpj0);
        const float hn1 = fast_tanh((j ? u11 : u10) + xpj1);

        if (active) {
            hw0[own] = hn0;                 // smem for the recurrence (fp32)
            hw1[own] = hn1;
            hs0[0] = __float2half_rn(hn0);  // fp16 trajectory (dead-end)
            hs1[0] = __float2half_rn(hn1);
        }
        hs0 += PADHS;
        hs1 += PADHS;

        group_bar(barid);                   // h_{t+1} published for this group

        // swap read/write buffers; advance x
        const float* tp;
        tp = hb0; hb0 = hw0; hw0 = (float*)tp;
        tp = hb1; hb1 = hw1; hw1 = (float*)tp;
        xc0 = xn0;
        xc1 = xn1;
    }
}

// ============================================================================
// Kernel 2: out[b,t] = W_fc . h[b,t] + b_fc.  Warp per (b,t); fp16 rows of
// 208 B -> 26 lanes x LDG.64, fp32 accumulation. DRAM-bound on 218 MB.
// ============================================================================
#define K2_BLOCK 256
#define K2_GRID  2048

__global__ void __launch_bounds__(K2_BLOCK)
proj_kernel(const float* __restrict__ W_fc,   // [1, 100]
            const float* __restrict__ b_fc,   // [1]
            float* __restrict__ out)          // [512*2048]
{
    const int lane  = threadIdx.x & 31;
    const int warp  = blockIdx.x * (K2_BLOCK / 32) + (threadIdx.x >> 5);
    const int nwarp = K2_GRID * (K2_BLOCK / 32);

    // lane k (<26) owns fp16 h-slots [4k, 4k+4); weights 0 beyond 99
    const bool ract = (lane < 26);
    float wf0 = 0.f, wf1 = 0.f, wf2 = 0.f, wf3 = 0.f;
    if (ract) {
        const int k = lane * 4;
        wf0 = (k + 0 < HDIM) ? W_fc[k + 0] : 0.0f;
        wf1 = (k + 1 < HDIM) ? W_fc[k + 1] : 0.0f;
        wf2 = (k + 2 < HDIM) ? W_fc[k + 2] : 0.0f;
        wf3 = (k + 3 < HDIM) ? W_fc[k + 3] : 0.0f;
    }
    const float bias = b_fc[0];

    const int total = 512 * TLEN;
    #pragma unroll 1
    for (int bt = warp; bt < total; bt += nwarp) {
        float s = 0.0f;
        if (ract) {
            const uint2 v = *reinterpret_cast<const uint2*>(
                Hs + (size_t)bt * PADHS + lane * 4);
            __half2 p0 = *reinterpret_cast<const __half2*>(&v.x);
            __half2 p1 = *reinterpret_cast<const __half2*>(&v.y);
            float2 f0 = __half22float2(p0);
            float2 f1 = __half22float2(p1);
            s = f0.x * wf0;
            s = fmaf(f0.y, wf1, s);
            s = fmaf(f1.x, wf2, s);
            s = fmaf(f1.y, wf3, s);
        }
        s += __shfl_xor_sync(0xFFFFFFFFu, s, 1);
        s += __shfl_xor_sync(0xFFFFFFFFu, s, 2);
        s += __shfl_xor_sync(0xFFFFFFFFu, s, 4);
        s += __shfl_xor_sync(0xFFFFFFFFu, s, 8);
        s += __shfl_xor_sync(0xFFFFFFFFu, s, 16);
        if (lane == 0)
            out[bt] = s + bias;
    }
}

extern "C" void kernel_launch(void* const* d_in, const int* in_sizes, int n_in,
                              void* d_out, int out_size) {
    const float* x    = (const float*)d_in[0];  // [512,2048,4]
    const float* W_ih = (const float*)d_in[1];  // [100,4]
    const float* W_hh = (const float*)d_in[2];  // [100,100]
    const float* W_fc = (const float*)d_in[3];  // [1,100]
    const float* b_fc = (const float*)d_in[4];  // [1]
    float* out = (float*)d_out;                 // [512,2048,1]

    crnn_step_kernel<<<NBLOCKS, BLOCK_T>>>(x, W_ih, W_hh);
    proj_kernel<<<K2_GRID, K2_BLOCK>>>(W_fc, b_fc, out);
}